// round 3
// baseline (speedup 1.0000x reference)
#include <cuda_runtime.h>
#include <cstdint>

#define B_   1024
#define V_   50257
#define E_   128
#define NCB  393            // ceil(V_/128)
#define GEMM_SMEM (2*128*132*4)

__device__ int   g_idx[B_];
__device__ __align__(16) float g_H[B_*E_];
__device__ float g_pmax[B_*NCB];
__device__ float g_psum[B_*NCB];
__device__ float g_lse[B_];

__device__ __forceinline__ unsigned f2tf(float f){
    unsigned u; asm("cvt.rna.tf32.f32 %0, %1;" : "=r"(u) : "f"(f)); return u;
}
__device__ __forceinline__ float neg_inf(){ return __int_as_float(0xff800000); }

// ---------------------------------------------------------------- K1: find one-hot index per row
__global__ void k_find(const float* __restrict__ xs){
    const int nf4 = (B_*V_)/4;
    for (int i = blockIdx.x*blockDim.x + threadIdx.x; i < nf4; i += gridDim.x*blockDim.x){
        float4 v = reinterpret_cast<const float4*>(xs)[i];
        if (v.x!=0.f || v.y!=0.f || v.z!=0.f || v.w!=0.f){
            float a[4] = {v.x, v.y, v.z, v.w};
            #pragma unroll
            for (int j = 0; j < 4; j++){
                if (a[j] != 0.f){
                    int f = i*4 + j;
                    g_idx[f / V_] = f % V_;
                }
            }
        }
    }
}

// ---------------------------------------------------------------- K2: H = EMBEDM[idx] @ metric
__global__ void k_embed(const float* __restrict__ EM, const float* __restrict__ metric){
    __shared__ float e[E_];
    const int row = blockIdx.x, t = threadIdx.x;
    e[t] = EM[(size_t)g_idx[row]*E_ + t];
    __syncthreads();
    float acc = 0.f;
    #pragma unroll 8
    for (int k = 0; k < E_; k++) acc += e[k] * metric[k*E_ + t];
    g_H[row*E_ + t] = acc;
}

// ---------------------------------------------------------------- K3: scores GEMM + partial softmax stats
// CTA tile 128(M) x 128(N), K=128 fully resident. 256 threads = 8 warps (4M x 2N),
// warp tile 32x64 via mma.sync.m16n8k8 tf32.
__global__ void __launch_bounds__(256,1) k_gemm(const float* __restrict__ neg, float* __restrict__ out){
    extern __shared__ unsigned sm[];
    unsigned* As = sm;              // [128][132] tf32 bits
    unsigned* Bs = sm + 128*132;    // [128][132]
    __shared__ float redm[128][2];
    __shared__ float reds[128][2];

    const int tid   = threadIdx.x;
    const int mBase = blockIdx.y * 128;
    const int nBase = blockIdx.x * 128;
    const bool full = (nBase + 128 <= V_);

    // Load A tile (H rows)
    {
        const float4* aSrc = reinterpret_cast<const float4*>(g_H + mBase*E_);
        #pragma unroll 4
        for (int i = tid; i < 4096; i += 256){
            float4 v = aSrc[i];
            unsigned* d = As + (i>>5)*132 + ((i&31)<<2);
            d[0]=f2tf(v.x); d[1]=f2tf(v.y); d[2]=f2tf(v.z); d[3]=f2tf(v.w);
        }
    }
    // Load B tile (NEGEMBEDM rows), zero-padded past V_
    {
        #pragma unroll 4
        for (int i = tid; i < 4096; i += 256){
            int r = i>>5, c = (i&31)<<2;
            int n = nBase + r;
            float4 v = make_float4(0.f,0.f,0.f,0.f);
            if (n < V_) v = *reinterpret_cast<const float4*>(neg + (size_t)n*E_ + c);
            unsigned* d = Bs + r*132 + c;
            d[0]=f2tf(v.x); d[1]=f2tf(v.y); d[2]=f2tf(v.z); d[3]=f2tf(v.w);
        }
    }
    __syncthreads();

    const int warp = tid >> 5, lane = tid & 31;
    const int wm = warp & 3, wn = warp >> 2;
    const int rowW = wm*32, colW = wn*64;
    const int lr = lane >> 2, lc = lane & 3;

    float acc[2][8][4];
    #pragma unroll
    for (int mf=0; mf<2; mf++)
        #pragma unroll
        for (int nf=0; nf<8; nf++)
            #pragma unroll
            for (int r=0; r<4; r++) acc[mf][nf][r] = 0.f;

    #pragma unroll
    for (int ks = 0; ks < 16; ks++){
        const int k0 = ks*8;
        unsigned a[2][4];
        #pragma unroll
        for (int mf=0; mf<2; mf++){
            const unsigned* p = As + (rowW + mf*16 + lr)*132 + k0 + lc;
            a[mf][0] = p[0];       a[mf][2] = p[4];
            a[mf][1] = p[8*132];   a[mf][3] = p[8*132+4];
        }
        unsigned b[8][2];
        #pragma unroll
        for (int nf=0; nf<8; nf++){
            const unsigned* p = Bs + (colW + nf*8 + lr)*132 + k0 + lc;
            b[nf][0] = p[0];  b[nf][1] = p[4];
        }
        #pragma unroll
        for (int mf=0; mf<2; mf++)
            #pragma unroll
            for (int nf=0; nf<8; nf++)
                asm volatile(
                    "mma.sync.aligned.m16n8k8.row.col.f32.tf32.tf32.f32 "
                    "{%0,%1,%2,%3},{%4,%5,%6,%7},{%8,%9},{%0,%1,%2,%3};"
                    : "+f"(acc[mf][nf][0]), "+f"(acc[mf][nf][1]),
                      "+f"(acc[mf][nf][2]), "+f"(acc[mf][nf][3])
                    : "r"(a[mf][0]), "r"(a[mf][1]), "r"(a[mf][2]), "r"(a[mf][3]),
                      "r"(b[nf][0]), "r"(b[nf][1]));
    }

    // -------- Phase A: per-row tile max (quad shuffle-reduce, then across the 2 N-warps)
    #pragma unroll
    for (int mf=0; mf<2; mf++){
        #pragma unroll
        for (int h=0; h<2; h++){
            float m = neg_inf();
            #pragma unroll
            for (int nf=0; nf<8; nf++){
                int n0 = nBase + colW + nf*8 + lc*2;
                float v0 = acc[mf][nf][h*2], v1 = acc[mf][nf][h*2+1];
                if (full || n0   < V_) m = fmaxf(m, v0);
                if (full || n0+1 < V_) m = fmaxf(m, v1);
            }
            m = fmaxf(m, __shfl_xor_sync(0xffffffffu, m, 1));
            m = fmaxf(m, __shfl_xor_sync(0xffffffffu, m, 2));
            if (lc == 0) redm[rowW + mf*16 + h*8 + lr][wn] = m;
        }
    }
    __syncthreads();

    // -------- Phase B: per-row tile sumexp against the tile max
    #pragma unroll
    for (int mf=0; mf<2; mf++){
        #pragma unroll
        for (int h=0; h<2; h++){
            const int row = rowW + mf*16 + h*8 + lr;
            const float M = fmaxf(redm[row][0], redm[row][1]);
            float s = 0.f;
            #pragma unroll
            for (int nf=0; nf<8; nf++){
                int n0 = nBase + colW + nf*8 + lc*2;
                float v0 = acc[mf][nf][h*2], v1 = acc[mf][nf][h*2+1];
                if (full || n0   < V_) s += __expf(v0 - M);
                if (full || n0+1 < V_) s += __expf(v1 - M);
            }
            s += __shfl_xor_sync(0xffffffffu, s, 1);
            s += __shfl_xor_sync(0xffffffffu, s, 2);
            if (lc == 0) reds[row][wn] = s;
        }
    }
    __syncthreads();

    if (tid < 128){
        const float M = fmaxf(redm[tid][0], redm[tid][1]);
        const float S = reds[tid][0] + reds[tid][1];
        const int gr = mBase + tid;
        g_pmax[gr*NCB + blockIdx.x] = M;
        g_psum[gr*NCB + blockIdx.x] = S;
    }

    // -------- store scores (scalar stores: rows are only 4B-aligned since V_ is odd)
    #pragma unroll
    for (int mf=0; mf<2; mf++){
        #pragma unroll
        for (int h=0; h<2; h++){
            const int grow = mBase + rowW + mf*16 + h*8 + lr;
            float* orow = out + (size_t)grow * V_;
            #pragma unroll
            for (int nf=0; nf<8; nf++){
                int n0 = nBase + colW + nf*8 + lc*2;
                float v0 = acc[mf][nf][h*2], v1 = acc[mf][nf][h*2+1];
                if (full || n0   < V_) orow[n0]   = v0;
                if (full || n0+1 < V_) orow[n0+1] = v1;
            }
        }
    }
}

// ---------------------------------------------------------------- K4: merge partials -> lse per row
__global__ void k_lse(){
    const int row = blockIdx.x;
    const int t = threadIdx.x;  // 128
    float m = neg_inf(), s = 0.f;
    for (int i = t; i < NCB; i += 128){
        float pm = g_pmax[row*NCB + i];
        float ps = g_psum[row*NCB + i];
        if (pm > m){ s = s*__expf(m - pm) + ps; m = pm; }
        else       { s += ps*__expf(pm - m); }
    }
    #pragma unroll
    for (int o = 16; o; o >>= 1){
        float om = __shfl_xor_sync(0xffffffffu, m, o);
        float os = __shfl_xor_sync(0xffffffffu, s, o);
        if (om > m){ s = s*__expf(m - om) + os; m = om; }
        else       { s += os*__expf(om - m); }
    }
    __shared__ float wm[4], ws[4];
    if ((t & 31) == 0){ wm[t>>5] = m; ws[t>>5] = s; }
    __syncthreads();
    if (t == 0){
        m = wm[0]; s = ws[0];
        #pragma unroll
        for (int w = 1; w < 4; w++){
            float om = wm[w], os = ws[w];
            if (om > m){ s = s*__expf(m - om) + os; m = om; }
            else       { s += os*__expf(om - m); }
        }
        g_lse[row] = m + logf(s);
    }
}

// ---------------------------------------------------------------- K5: out -= lse[row]
__global__ void k_fix(float* __restrict__ out){
    const int row = blockIdx.y;
    const float l = g_lse[row];
    float* o = out + (size_t)row * V_;
    const int base = blockIdx.x*1024 + threadIdx.x;
    #pragma unroll
    for (int j = 0; j < 4; j++){
        int c = base + j*256;
        if (c < V_) o[c] -= l;
    }
}

// ---------------------------------------------------------------- launch
extern "C" void kernel_launch(void* const* d_in, const int* in_sizes, int n_in,
                              void* d_out, int out_size){
    const float* xs     = (const float*)d_in[0];
    const float* metric = (const float*)d_in[1];
    const float* EM     = (const float*)d_in[2];
    const float* NEG    = (const float*)d_in[3];
    float* out = (float*)d_out;

    cudaFuncSetAttribute(k_gemm, cudaFuncAttributeMaxDynamicSharedMemorySize, GEMM_SMEM);

    k_find <<<4096, 256>>>(xs);
    k_embed<<<B_, E_>>>(EM, metric);
    k_gemm <<<dim3(NCB, B_/128), 256, GEMM_SMEM>>>(NEG, out);
    k_lse  <<<B_, 128>>>();
    k_fix  <<<dim3((V_ + 1023)/1024, B_), 256>>>(out);
}

// round 5
// speedup vs baseline: 1.0108x; 1.0108x over previous
#include <cuda_runtime.h>
#include <cstdint>

#define B_   1024
#define V_   50257
#define E_   128
#define NCB  393            // ceil(V_/128)
#define LDT  132            // smem row stride in floats
#define TILEF (128*LDT)     // floats per tile buffer
#define GEMM_SMEM (3*TILEF*4)   // A + B0 + B1 = 202,752 bytes
#define NSPLIT 18           // N-block strips -> grid.x

__device__ int   g_idx[B_];
__device__ __align__(16) float g_H[B_*E_];
__device__ float g_pmax[B_*NCB];
__device__ float g_psum[B_*NCB];
__device__ float g_lse[B_];

__device__ __forceinline__ float neg_inf(){ return __int_as_float(0xff800000); }

__device__ __forceinline__ uint32_t smem_u32(const void* p){
    uint32_t a;
    asm("{ .reg .u64 t; cvta.to.shared.u64 t, %1; cvt.u32.u64 %0, t; }" : "=r"(a) : "l"(p));
    return a;
}
__device__ __forceinline__ void cp16(uint32_t dst, const void* src, unsigned srcBytes){
    asm volatile("cp.async.cg.shared.global [%0], [%1], 16, %2;"
                 :: "r"(dst), "l"(src), "r"(srcBytes) : "memory");
}
__device__ __forceinline__ void cp_commit(){ asm volatile("cp.async.commit_group;" ::: "memory"); }
template<int N>
__device__ __forceinline__ void cp_wait(){ asm volatile("cp.async.wait_group %0;" :: "n"(N) : "memory"); }

// ---------------- K1: find one-hot index per row ----------------
__global__ void k_find(const float* __restrict__ xs){
    const int nf4 = (B_*V_)/4;
    for (int i = blockIdx.x*blockDim.x + threadIdx.x; i < nf4; i += gridDim.x*blockDim.x){
        float4 v = reinterpret_cast<const float4*>(xs)[i];
        if (v.x!=0.f || v.y!=0.f || v.z!=0.f || v.w!=0.f){
            float a[4] = {v.x, v.y, v.z, v.w};
            #pragma unroll
            for (int j = 0; j < 4; j++){
                if (a[j] != 0.f){
                    int f = i*4 + j;
                    g_idx[f / V_] = f % V_;
                }
            }
        }
    }
}

// ---------------- K2: H = EMBEDM[idx] @ metric ----------------
__global__ void k_embed(const float* __restrict__ EM, const float* __restrict__ metric){
    __shared__ float e[E_];
    const int row = blockIdx.x, t = threadIdx.x;
    e[t] = EM[(size_t)g_idx[row]*E_ + t];
    __syncthreads();
    float acc = 0.f;
    #pragma unroll 8
    for (int k = 0; k < E_; k++) acc += e[k] * metric[k*E_ + t];
    g_H[row*E_ + t] = acc;
}

// ---------------- K3: persistent GEMM + partial softmax stats ----------------
// grid (NSPLIT, 8). Each CTA: fixed M tile (128 rows), iterates N blocks
// nb = gx, gx+NSPLIT, ... < NCB with cp.async double-buffered B tiles.
// 256 threads = 8 warps (4M x 2N), warp tile 32x64, mma.sync m16n8k8 tf32
// (raw f32 bits fed to HMMA -> HW truncates to tf32; no cvt needed).
__global__ void __launch_bounds__(256,1) k_gemm(const float* __restrict__ neg, float* __restrict__ out){
    extern __shared__ __align__(16) float sm[];
    float* As = sm;                  // [128][132]
    float* Bs[2] = { sm + TILEF, sm + 2*TILEF };
    __shared__ float redm[128][2];
    __shared__ float reds[128][2];

    const int tid   = threadIdx.x;
    const int mBase = blockIdx.y * 128;
    const int gx    = blockIdx.x;

    const int warp = tid >> 5, lane = tid & 31;
    const int wm = warp & 3, wn = warp >> 2;
    const int rowW = wm*32, colW = wn*64;
    const int lr = lane >> 2, lc = lane & 3;

    // ---- A tile once (plain LDG -> STS, raw f32) ----
    {
        const float4* aSrc = reinterpret_cast<const float4*>(g_H + (size_t)mBase*E_);
        #pragma unroll 4
        for (int i = tid; i < 4096; i += 256){
            float4 v = aSrc[i];
            float* d = As + (i>>5)*LDT + ((i&31)<<2);
            d[0]=v.x; d[1]=v.y; d[2]=v.z; d[3]=v.w;
        }
    }

    // number of tiles for this strip
    int nT = 0; for (int nb = gx; nb < NCB; nb += NSPLIT) nT++;

    // ---- issue B tile 0 ----
    {
        const int nBase = gx * 128;
        const uint32_t bb = smem_u32(Bs[0]);
        #pragma unroll 4
        for (int i = tid; i < 4096; i += 256){
            int r = i>>5, c = (i&31)<<2;
            int n = nBase + r;
            unsigned ok = (n < V_) ? 16u : 0u;
            const float* src = neg + (size_t)(n < V_ ? n : 0)*E_ + c;
            cp16(bb + (uint32_t)(r*LDT + c)*4u, src, ok);
        }
        cp_commit();
    }
    __syncthreads();   // A tile visible to all warps

    for (int j = 0; j < nT; j++){
        const int nb    = gx + j*NSPLIT;
        const int nBase = nb * 128;
        const bool full = (nBase + 128 <= V_);
        const int cur   = j & 1;

        // ---- prefetch next B tile into other buffer ----
        if (j + 1 < nT){
            const int nBase2 = (gx + (j+1)*NSPLIT) * 128;
            const uint32_t bb = smem_u32(Bs[cur ^ 1]);
            #pragma unroll 4
            for (int i = tid; i < 4096; i += 256){
                int r = i>>5, c = (i&31)<<2;
                int n = nBase2 + r;
                unsigned ok = (n < V_) ? 16u : 0u;
                const float* src = neg + (size_t)(n < V_ ? n : 0)*E_ + c;
                cp16(bb + (uint32_t)(r*LDT + c)*4u, src, ok);
            }
            cp_commit();
            cp_wait<1>();     // tile j complete; tile j+1 may fly
        } else {
            cp_wait<0>();
        }
        __syncthreads();

        const unsigned* Au = reinterpret_cast<const unsigned*>(As);
        const unsigned* Bu = reinterpret_cast<const unsigned*>(Bs[cur]);

        float acc[2][8][4];
        #pragma unroll
        for (int mf=0; mf<2; mf++)
            #pragma unroll
            for (int nf=0; nf<8; nf++)
                #pragma unroll
                for (int r=0; r<4; r++) acc[mf][nf][r] = 0.f;

        #pragma unroll
        for (int ks = 0; ks < 16; ks++){
            const int k0 = ks*8;
            unsigned a[2][4];
            #pragma unroll
            for (int mf=0; mf<2; mf++){
                const unsigned* p = Au + (rowW + mf*16 + lr)*LDT + k0 + lc;
                a[mf][0] = p[0];       a[mf][2] = p[4];
                a[mf][1] = p[8*LDT];   a[mf][3] = p[8*LDT+4];
            }
            unsigned b[8][2];
            #pragma unroll
            for (int nf=0; nf<8; nf++){
                const unsigned* p = Bu + (colW + nf*8 + lr)*LDT + k0 + lc;
                b[nf][0] = p[0];  b[nf][1] = p[4];
            }
            #pragma unroll
            for (int mf=0; mf<2; mf++)
                #pragma unroll
                for (int nf=0; nf<8; nf++)
                    asm volatile(
                        "mma.sync.aligned.m16n8k8.row.col.f32.tf32.tf32.f32 "
                        "{%0,%1,%2,%3},{%4,%5,%6,%7},{%8,%9},{%0,%1,%2,%3};"
                        : "+f"(acc[mf][nf][0]), "+f"(acc[mf][nf][1]),
                          "+f"(acc[mf][nf][2]), "+f"(acc[mf][nf][3])
                        : "r"(a[mf][0]), "r"(a[mf][1]), "r"(a[mf][2]), "r"(a[mf][3]),
                          "r"(b[nf][0]), "r"(b[nf][1]));
        }

        // -------- Phase A: per-row tile max --------
        #pragma unroll
        for (int mf=0; mf<2; mf++){
            #pragma unroll
            for (int h=0; h<2; h++){
                float m = neg_inf();
                #pragma unroll
                for (int nf=0; nf<8; nf++){
                    int n0 = nBase + colW + nf*8 + lc*2;
                    float v0 = acc[mf][nf][h*2], v1 = acc[mf][nf][h*2+1];
                    if (full || n0   < V_) m = fmaxf(m, v0);
                    if (full || n0+1 < V_) m = fmaxf(m, v1);
                }
                m = fmaxf(m, __shfl_xor_sync(0xffffffffu, m, 1));
                m = fmaxf(m, __shfl_xor_sync(0xffffffffu, m, 2));
                if (lc == 0) redm[rowW + mf*16 + h*8 + lr][wn] = m;
            }
        }
        __syncthreads();

        // -------- Phase B: per-row tile sumexp --------
        #pragma unroll
        for (int mf=0; mf<2; mf++){
            #pragma unroll
            for (int h=0; h<2; h++){
                const int row = rowW + mf*16 + h*8 + lr;
                const float M = fmaxf(redm[row][0], redm[row][1]);
                float s = 0.f;
                #pragma unroll
                for (int nf=0; nf<8; nf++){
                    int n0 = nBase + colW + nf*8 + lc*2;
                    float v0 = acc[mf][nf][h*2], v1 = acc[mf][nf][h*2+1];
                    if (full || n0   < V_) s += __expf(v0 - M);
                    if (full || n0+1 < V_) s += __expf(v1 - M);
                }
                s += __shfl_xor_sync(0xffffffffu, s, 1);
                s += __shfl_xor_sync(0xffffffffu, s, 2);
                if (lc == 0) reds[row][wn] = s;
            }
        }
        __syncthreads();

        if (tid < 128){
            const float M = fmaxf(redm[tid][0], redm[tid][1]);
            const float S = reds[tid][0] + reds[tid][1];
            const int gr = mBase + tid;
            g_pmax[gr*NCB + nb] = M;
            g_psum[gr*NCB + nb] = S;
        }

        // -------- store scores (scalar: V_ odd -> rows only 4B aligned) --------
        #pragma unroll
        for (int mf=0; mf<2; mf++){
            #pragma unroll
            for (int h=0; h<2; h++){
                const int grow = mBase + rowW + mf*16 + h*8 + lr;
                float* orow = out + (size_t)grow * V_;
                #pragma unroll
                for (int nf=0; nf<8; nf++){
                    int n0 = nBase + colW + nf*8 + lc*2;
                    float v0 = acc[mf][nf][h*2], v1 = acc[mf][nf][h*2+1];
                    if (full || n0   < V_) orow[n0]   = v0;
                    if (full || n0+1 < V_) orow[n0+1] = v1;
                }
            }
        }
        __syncthreads();   // protect redm/reds and B buffer reuse
    }
}

// ---------------- K4: merge partials -> lse per row ----------------
__global__ void k_lse(){
    const int row = blockIdx.x;
    const int t = threadIdx.x;  // 128
    float m = neg_inf(), s = 0.f;
    for (int i = t; i < NCB; i += 128){
        float pm = g_pmax[row*NCB + i];
        float ps = g_psum[row*NCB + i];
        if (pm > m){ s = s*__expf(m - pm) + ps; m = pm; }
        else       { s += ps*__expf(pm - m); }
    }
    #pragma unroll
    for (int o = 16; o; o >>= 1){
        float om = __shfl_xor_sync(0xffffffffu, m, o);
        float os = __shfl_xor_sync(0xffffffffu, s, o);
        if (om > m){ s = s*__expf(m - om) + os; m = om; }
        else       { s += os*__expf(om - m); }
    }
    __shared__ float wm[4], ws[4];
    if ((t & 31) == 0){ wm[t>>5] = m; ws[t>>5] = s; }
    __syncthreads();
    if (t == 0){
        m = wm[0]; s = ws[0];
        #pragma unroll
        for (int w = 1; w < 4; w++){
            float om = wm[w], os = ws[w];
            if (om > m){ s = s*__expf(m - om) + os; m = om; }
            else       { s += os*__expf(om - m); }
        }
        g_lse[row] = m + logf(s);
    }
}

// ---------------- K5: out -= lse[row] ----------------
__global__ void k_fix(float* __restrict__ out){
    const int row = blockIdx.y;
    const float l = g_lse[row];
    float* o = out + (size_t)row * V_;
    const int base = blockIdx.x*1024 + threadIdx.x;
    #pragma unroll
    for (int j = 0; j < 4; j++){
        int c = base + j*256;
        if (c < V_) o[c] -= l;
    }
}

// ---------------- launch ----------------
extern "C" void kernel_launch(void* const* d_in, const int* in_sizes, int n_in,
                              void* d_out, int out_size){
    const float* xs     = (const float*)d_in[0];
    const float* metric = (const float*)d_in[1];
    const float* EM     = (const float*)d_in[2];
    const float* NEG    = (const float*)d_in[3];
    float* out = (float*)d_out;

    cudaFuncSetAttribute(k_gemm, cudaFuncAttributeMaxDynamicSharedMemorySize, GEMM_SMEM);

    k_find <<<4096, 256>>>(xs);
    k_embed<<<B_, E_>>>(EM, metric);
    k_gemm <<<dim3(NSPLIT, B_/128), 256, GEMM_SMEM>>>(NEG, out);
    k_lse  <<<B_, 128>>>();
    k_fix  <<<dim3((V_ + 1023)/1024, B_), 256>>>(out);
}

// round 7
// speedup vs baseline: 1.2367x; 1.2235x over previous
#include <cuda_runtime.h>
#include <cuda_fp16.h>
#include <cstdint>

#define B_   1024
#define V_   50257
#define E_   128
#define NCB  393            // ceil(V_/128)
#define NSPLIT 36           // N strips -> grid.x (288 CTAs = 2/SM)
#define LDH  136            // halves per smem row (128 + 8 pad)
#define LDW  68             // uint32 (half2) stride
#define TILE_BYTES (128*LDH*2)      // 34816
#define GEMM_SMEM  (2*TILE_BYTES)   // A + B = 69632

__device__ int   g_idx[B_];
__device__ __align__(16) float g_H[B_*E_];
__device__ float g_pmax[B_*NCB];
__device__ float g_psum[B_*NCB];
__device__ float g_lse[B_];

__device__ __forceinline__ float neg_inf(){ return __int_as_float(0xff800000); }

__device__ __forceinline__ uint32_t pack2(float x, float y){
    __half2 h = __floats2half2_rn(x, y);
    return *reinterpret_cast<uint32_t*>(&h);
}

// ---------------- K1: find one-hot index per row ----------------
__global__ void k_find(const float* __restrict__ xs){
    const int nf4 = (B_*V_)/4;
    for (int i = blockIdx.x*blockDim.x + threadIdx.x; i < nf4; i += gridDim.x*blockDim.x){
        float4 v = reinterpret_cast<const float4*>(xs)[i];
        if (v.x!=0.f || v.y!=0.f || v.z!=0.f || v.w!=0.f){
            float a[4] = {v.x, v.y, v.z, v.w};
            #pragma unroll
            for (int j = 0; j < 4; j++){
                if (a[j] != 0.f){
                    int f = i*4 + j;
                    g_idx[f / V_] = f % V_;
                }
            }
        }
    }
}

// ---------------- K2: H = EMBEDM[idx] @ metric ----------------
__global__ void k_embed(const float* __restrict__ EM, const float* __restrict__ metric){
    __shared__ float e[E_];
    const int row = blockIdx.x, t = threadIdx.x;
    e[t] = EM[(size_t)g_idx[row]*E_ + t];
    __syncthreads();
    float acc = 0.f;
    #pragma unroll 8
    for (int k = 0; k < E_; k++) acc += e[k] * metric[k*E_ + t];
    g_H[row*E_ + t] = acc;
}

// ---------------- K3: persistent fp16 GEMM + partial softmax stats ----------------
// grid (NSPLIT, 8), 256 thr = 8 warps (4M x 2N), warp tile 32x64,
// mma.sync.m16n8k16.f16 (fp32 accum). 2 CTAs/SM for cross-CTA pipe overlap.
__global__ void __launch_bounds__(256,2) k_gemm(const float* __restrict__ neg, float* __restrict__ out){
    extern __shared__ __align__(16) unsigned char smraw[];
    uint32_t* Au = reinterpret_cast<uint32_t*>(smraw);               // A: [128][LDH] halves
    uint32_t* Bu = reinterpret_cast<uint32_t*>(smraw + TILE_BYTES);  // B: [128][LDH] halves
    __shared__ float redm[128][2];
    __shared__ float reds[128][2];

    const int tid   = threadIdx.x;
    const int mBase = blockIdx.y * 128;
    const int gx    = blockIdx.x;

    const int warp = tid >> 5, lane = tid & 31;
    const int wm = warp & 3, wn = warp >> 2;
    const int rowW = wm*32, colW = wn*64;
    const int lr = lane >> 2, lc = lane & 3;

    // ---- A tile once: f32 -> f16 (RN) ----
    {
        const float4* aSrc = reinterpret_cast<const float4*>(g_H + (size_t)mBase*E_);
        #pragma unroll 4
        for (int i = tid; i < 4096; i += 256){
            float4 v = aSrc[i];
            int row = i >> 5, c4 = (i & 31) << 2;
            uint2 w = make_uint2(pack2(v.x, v.y), pack2(v.z, v.w));
            *reinterpret_cast<uint2*>(Au + row*LDW + (c4 >> 1)) = w;
        }
    }

    for (int nb = gx; nb < NCB; nb += NSPLIT){
        const int nBase = nb * 128;
        const bool full = (nBase + 128 <= V_);

        // ---- B tile: f32 LDG -> f16 -> STS (zero pad past V_) ----
        #pragma unroll 4
        for (int i = tid; i < 4096; i += 256){
            int row = i >> 5, c4 = (i & 31) << 2;
            int n = nBase + row;
            float4 v = make_float4(0.f, 0.f, 0.f, 0.f);
            if (n < V_) v = *reinterpret_cast<const float4*>(neg + (size_t)n*E_ + c4);
            uint2 w = make_uint2(pack2(v.x, v.y), pack2(v.z, v.w));
            *reinterpret_cast<uint2*>(Bu + row*LDW + (c4 >> 1)) = w;
        }
        __syncthreads();

        float acc[2][8][4];
        #pragma unroll
        for (int mf=0; mf<2; mf++)
            #pragma unroll
            for (int nf=0; nf<8; nf++)
                #pragma unroll
                for (int r=0; r<4; r++) acc[mf][nf][r] = 0.f;

        #pragma unroll
        for (int ks = 0; ks < 8; ks++){
            const int k0w = ks*8;       // 16 halves = 8 words per k-step
            uint32_t a[2][4];
            #pragma unroll
            for (int mf=0; mf<2; mf++){
                const uint32_t* p0 = Au + (rowW + mf*16 + lr)*LDW + k0w + lc;
                const uint32_t* p1 = p0 + 8*LDW;
                a[mf][0] = p0[0]; a[mf][1] = p1[0];
                a[mf][2] = p0[4]; a[mf][3] = p1[4];
            }
            uint32_t b[8][2];
            #pragma unroll
            for (int nf=0; nf<8; nf++){
                const uint32_t* p = Bu + (colW + nf*8 + lr)*LDW + k0w + lc;
                b[nf][0] = p[0];  b[nf][1] = p[4];
            }
            #pragma unroll
            for (int mf=0; mf<2; mf++)
                #pragma unroll
                for (int nf=0; nf<8; nf++)
                    asm volatile(
                        "mma.sync.aligned.m16n8k16.row.col.f32.f16.f16.f32 "
                        "{%0,%1,%2,%3},{%4,%5,%6,%7},{%8,%9},{%0,%1,%2,%3};"
                        : "+f"(acc[mf][nf][0]), "+f"(acc[mf][nf][1]),
                          "+f"(acc[mf][nf][2]), "+f"(acc[mf][nf][3])
                        : "r"(a[mf][0]), "r"(a[mf][1]), "r"(a[mf][2]), "r"(a[mf][3]),
                          "r"(b[nf][0]), "r"(b[nf][1]));
        }

        // -------- Phase A: per-row tile max --------
        #pragma unroll
        for (int mf=0; mf<2; mf++){
            #pragma unroll
            for (int h=0; h<2; h++){
                float m = neg_inf();
                #pragma unroll
                for (int nf=0; nf<8; nf++){
                    int n0 = nBase + colW + nf*8 + lc*2;
                    float v0 = acc[mf][nf][h*2], v1 = acc[mf][nf][h*2+1];
                    if (full || n0   < V_) m = fmaxf(m, v0);
                    if (full || n0+1 < V_) m = fmaxf(m, v1);
                }
                m = fmaxf(m, __shfl_xor_sync(0xffffffffu, m, 1));
                m = fmaxf(m, __shfl_xor_sync(0xffffffffu, m, 2));
                if (lc == 0) redm[rowW + mf*16 + h*8 + lr][wn] = m;
            }
        }
        __syncthreads();

        // -------- Phase B: per-row tile sumexp --------
        #pragma unroll
        for (int mf=0; mf<2; mf++){
            #pragma unroll
            for (int h=0; h<2; h++){
                const int row = rowW + mf*16 + h*8 + lr;
                const float M = fmaxf(redm[row][0], redm[row][1]);
                float s = 0.f;
                #pragma unroll
                for (int nf=0; nf<8; nf++){
                    int n0 = nBase + colW + nf*8 + lc*2;
                    float v0 = acc[mf][nf][h*2], v1 = acc[mf][nf][h*2+1];
                    if (full || n0   < V_) s += __expf(v0 - M);
                    if (full || n0+1 < V_) s += __expf(v1 - M);
                }
                s += __shfl_xor_sync(0xffffffffu, s, 1);
                s += __shfl_xor_sync(0xffffffffu, s, 2);
                if (lc == 0) reds[row][wn] = s;
            }
        }
        __syncthreads();

        if (tid < 128){
            const float M = fmaxf(redm[tid][0], redm[tid][1]);
            const float S = reds[tid][0] + reds[tid][1];
            const int gr = mBase + tid;
            g_pmax[gr*NCB + nb] = M;
            g_psum[gr*NCB + nb] = S;
        }

        // -------- store scores (scalar: V_ odd -> rows only 4B aligned) --------
        #pragma unroll
        for (int mf=0; mf<2; mf++){
            #pragma unroll
            for (int h=0; h<2; h++){
                const int grow = mBase + rowW + mf*16 + h*8 + lr;
                float* orow = out + (size_t)grow * V_;
                #pragma unroll
                for (int nf=0; nf<8; nf++){
                    int n0 = nBase + colW + nf*8 + lc*2;
                    float v0 = acc[mf][nf][h*2], v1 = acc[mf][nf][h*2+1];
                    if (full || n0   < V_) orow[n0]   = v0;
                    if (full || n0+1 < V_) orow[n0+1] = v1;
                }
            }
        }
        __syncthreads();   // protect redm/reds + B tile reuse
    }
}

// ---------------- K4: merge partials -> lse per row ----------------
__global__ void k_lse(){
    const int row = blockIdx.x;
    const int t = threadIdx.x;  // 128
    float m = neg_inf(), s = 0.f;
    for (int i = t; i < NCB; i += 128){
        float pm = g_pmax[row*NCB + i];
        float ps = g_psum[row*NCB + i];
        if (pm > m){ s = s*__expf(m - pm) + ps; m = pm; }
        else       { s += ps*__expf(pm - m); }
    }
    #pragma unroll
    for (int o = 16; o; o >>= 1){
        float om = __shfl_xor_sync(0xffffffffu, m, o);
        float os = __shfl_xor_sync(0xffffffffu, s, o);
        if (om > m){ s = s*__expf(m - om) + os; m = om; }
        else       { s += os*__expf(om - m); }
    }
    __shared__ float wm[4], ws[4];
    if ((t & 31) == 0){ wm[t>>5] = m; ws[t>>5] = s; }
    __syncthreads();
    if (t == 0){
        m = wm[0]; s = ws[0];
        #pragma unroll
        for (int w = 1; w < 4; w++){
            float om = wm[w], os = ws[w];
            if (om > m){ s = s*__expf(m - om) + os; m = om; }
            else       { s += os*__expf(om - m); }
        }
        g_lse[row] = m + logf(s);
    }
}

// ---------------- K5: out -= lse[row] ----------------
__global__ void k_fix(float* __restrict__ out){
    const int row = blockIdx.y;
    const float l = g_lse[row];
    float* o = out + (size_t)row * V_;
    const int base = blockIdx.x*1024 + threadIdx.x;
    #pragma unroll
    for (int j = 0; j < 4; j++){
        int c = base + j*256;
        if (c < V_) o[c] -= l;
    }
}

// ---------------- launch ----------------
extern "C" void kernel_launch(void* const* d_in, const int* in_sizes, int n_in,
                              void* d_out, int out_size){
    const float* xs     = (const float*)d_in[0];
    const float* metric = (const float*)d_in[1];
    const float* EM     = (const float*)d_in[2];
    const float* NEG    = (const float*)d_in[3];
    float* out = (float*)d_out;

    cudaFuncSetAttribute(k_gemm, cudaFuncAttributeMaxDynamicSharedMemorySize, GEMM_SMEM);

    k_find <<<4096, 256>>>(xs);
    k_embed<<<B_, E_>>>(EM, metric);
    k_gemm <<<dim3(NSPLIT, B_/128), 256, GEMM_SMEM>>>(NEG, out);
    k_lse  <<<B_, 128>>>();
    k_fix  <<<dim3((V_ + 1023)/1024, B_), 256>>>(out);
}

// round 8
// speedup vs baseline: 1.4524x; 1.1744x over previous
#include <cuda_runtime.h>
#include <cuda_fp16.h>
#include <cstdint>

#define B_   1024
#define V_   50257
#define E_   128
#define NCB  393            // ceil(V_/128)
#define NSPLIT 36           // N strips -> grid.x (288 CTAs = 2/SM)
#define LDH  136            // halves per smem row (128 + 8 pad)
#define LDW  68             // uint32 (half2) stride
#define TILE_BYTES (128*LDH*2)      // 34816 (A and B tiles)
#define LDS_  130           // stage stride in floats
#define STAGE_BYTES (128*LDS_*4)    // 66560
#define GEMM_SMEM (TILE_BYTES + STAGE_BYTES)  // A + max(B, stage) = 101376

__device__ int   g_idx[B_];
__device__ __align__(16) float g_H[B_*E_];
__device__ float g_pmax[B_*NCB];
__device__ float g_psum[B_*NCB];
__device__ float g_lse[B_];

__device__ __forceinline__ float neg_inf(){ return __int_as_float(0xff800000); }

__device__ __forceinline__ uint32_t pack2(float x, float y){
    __half2 h = __floats2half2_rn(x, y);
    return *reinterpret_cast<uint32_t*>(&h);
}

// ---------------- K1: find one-hot index per row ----------------
__global__ void k_find(const float* __restrict__ xs){
    const int nf4 = (B_*V_)/4;
    for (int i = blockIdx.x*blockDim.x + threadIdx.x; i < nf4; i += gridDim.x*blockDim.x){
        float4 v = reinterpret_cast<const float4*>(xs)[i];
        if (v.x!=0.f || v.y!=0.f || v.z!=0.f || v.w!=0.f){
            float a[4] = {v.x, v.y, v.z, v.w};
            #pragma unroll
            for (int j = 0; j < 4; j++){
                if (a[j] != 0.f){
                    int f = i*4 + j;
                    g_idx[f / V_] = f % V_;
                }
            }
        }
    }
}

// ---------------- K2: H = EMBEDM[idx] @ metric ----------------
__global__ void k_embed(const float* __restrict__ EM, const float* __restrict__ metric){
    __shared__ float e[E_];
    const int row = blockIdx.x, t = threadIdx.x;
    e[t] = EM[(size_t)g_idx[row]*E_ + t];
    __syncthreads();
    float acc = 0.f;
    #pragma unroll 8
    for (int k = 0; k < E_; k++) acc += e[k] * metric[k*E_ + t];
    g_H[row*E_ + t] = acc;
}

// ---------------- K3: persistent fp16 GEMM + partial softmax stats ----------------
// grid (NSPLIT, 8), 256 thr = 8 warps (4M x 2N), warp tile 32x64,
// mma.sync.m16n8k16.f16 (fp32 accum). 2 CTAs/SM.
// Output staged through SMEM for fully-coalesced row-major stores.
__global__ void __launch_bounds__(256,2) k_gemm(const float* __restrict__ neg, float* __restrict__ out){
    extern __shared__ __align__(16) unsigned char smraw[];
    uint32_t* Au = reinterpret_cast<uint32_t*>(smraw);               // A: [128][LDH] halves
    uint32_t* Bu = reinterpret_cast<uint32_t*>(smraw + TILE_BYTES);  // B: [128][LDH] halves
    float*    Sg = reinterpret_cast<float*>(smraw + TILE_BYTES);     // stage overlays B (post-MMA)
    __shared__ float redm[128][2];
    __shared__ float reds[128][2];

    const int tid   = threadIdx.x;
    const int mBase = blockIdx.y * 128;
    const int gx    = blockIdx.x;

    const int warp = tid >> 5, lane = tid & 31;
    const int wm = warp & 3, wn = warp >> 2;
    const int rowW = wm*32, colW = wn*64;
    const int lr = lane >> 2, lc = lane & 3;

    // ---- A tile once: f32 -> f16 (RN) ----
    {
        const float4* aSrc = reinterpret_cast<const float4*>(g_H + (size_t)mBase*E_);
        #pragma unroll 4
        for (int i = tid; i < 4096; i += 256){
            float4 v = aSrc[i];
            int row = i >> 5, c4 = (i & 31) << 2;
            uint2 w = make_uint2(pack2(v.x, v.y), pack2(v.z, v.w));
            *reinterpret_cast<uint2*>(Au + row*LDW + (c4 >> 1)) = w;
        }
    }

    for (int nb = gx; nb < NCB; nb += NSPLIT){
        const int nBase = nb * 128;
        const int nValid = (V_ - nBase < 128) ? (V_ - nBase) : 128;
        const bool full = (nValid == 128);

        // ---- B tile: f32 LDG -> f16 -> STS (zero pad past V_) ----
        #pragma unroll 4
        for (int i = tid; i < 4096; i += 256){
            int row = i >> 5, c4 = (i & 31) << 2;
            int n = nBase + row;
            float4 v = make_float4(0.f, 0.f, 0.f, 0.f);
            if (n < V_) v = *reinterpret_cast<const float4*>(neg + (size_t)n*E_ + c4);
            uint2 w = make_uint2(pack2(v.x, v.y), pack2(v.z, v.w));
            *reinterpret_cast<uint2*>(Bu + row*LDW + (c4 >> 1)) = w;
        }
        __syncthreads();

        float acc[2][8][4];
        #pragma unroll
        for (int mf=0; mf<2; mf++)
            #pragma unroll
            for (int nf=0; nf<8; nf++)
                #pragma unroll
                for (int r=0; r<4; r++) acc[mf][nf][r] = 0.f;

        #pragma unroll
        for (int ks = 0; ks < 8; ks++){
            const int k0w = ks*8;       // 16 halves = 8 words per k-step
            uint32_t a[2][4];
            #pragma unroll
            for (int mf=0; mf<2; mf++){
                const uint32_t* p0 = Au + (rowW + mf*16 + lr)*LDW + k0w + lc;
                const uint32_t* p1 = p0 + 8*LDW;
                a[mf][0] = p0[0]; a[mf][1] = p1[0];
                a[mf][2] = p0[4]; a[mf][3] = p1[4];
            }
            uint32_t b[8][2];
            #pragma unroll
            for (int nf=0; nf<8; nf++){
                const uint32_t* p = Bu + (colW + nf*8 + lr)*LDW + k0w + lc;
                b[nf][0] = p[0];  b[nf][1] = p[4];
            }
            #pragma unroll
            for (int mf=0; mf<2; mf++)
                #pragma unroll
                for (int nf=0; nf<8; nf++)
                    asm volatile(
                        "mma.sync.aligned.m16n8k16.row.col.f32.f16.f16.f32 "
                        "{%0,%1,%2,%3},{%4,%5,%6,%7},{%8,%9},{%0,%1,%2,%3};"
                        : "+f"(acc[mf][nf][0]), "+f"(acc[mf][nf][1]),
                          "+f"(acc[mf][nf][2]), "+f"(acc[mf][nf][3])
                        : "r"(a[mf][0]), "r"(a[mf][1]), "r"(a[mf][2]), "r"(a[mf][3]),
                          "r"(b[nf][0]), "r"(b[nf][1]));
        }

        // -------- Phase A: per-row tile max --------
        #pragma unroll
        for (int mf=0; mf<2; mf++){
            #pragma unroll
            for (int h=0; h<2; h++){
                float m = neg_inf();
                #pragma unroll
                for (int nf=0; nf<8; nf++){
                    int n0 = nBase + colW + nf*8 + lc*2;
                    float v0 = acc[mf][nf][h*2], v1 = acc[mf][nf][h*2+1];
                    if (full || n0   < V_) m = fmaxf(m, v0);
                    if (full || n0+1 < V_) m = fmaxf(m, v1);
                }
                m = fmaxf(m, __shfl_xor_sync(0xffffffffu, m, 1));
                m = fmaxf(m, __shfl_xor_sync(0xffffffffu, m, 2));
                if (lc == 0) redm[rowW + mf*16 + h*8 + lr][wn] = m;
            }
        }
        __syncthreads();

        // -------- Phase B: per-row tile sumexp --------
        #pragma unroll
        for (int mf=0; mf<2; mf++){
            #pragma unroll
            for (int h=0; h<2; h++){
                const int row = rowW + mf*16 + h*8 + lr;
                const float M = fmaxf(redm[row][0], redm[row][1]);
                float s = 0.f;
                #pragma unroll
                for (int nf=0; nf<8; nf++){
                    int n0 = nBase + colW + nf*8 + lc*2;
                    float v0 = acc[mf][nf][h*2], v1 = acc[mf][nf][h*2+1];
                    if (full || n0   < V_) s += __expf(v0 - M);
                    if (full || n0+1 < V_) s += __expf(v1 - M);
                }
                s += __shfl_xor_sync(0xffffffffu, s, 1);
                s += __shfl_xor_sync(0xffffffffu, s, 2);
                if (lc == 0) reds[row][wn] = s;
            }
        }
        __syncthreads();

        if (tid < 128){
            const float M = fmaxf(redm[tid][0], redm[tid][1]);
            const float S = reds[tid][0] + reds[tid][1];
            const int gr = mBase + tid;
            g_pmax[gr*NCB + nb] = M;
            g_psum[gr*NCB + nb] = S;
        }
        // NOTE: B tile (Bu) is dead from here; Sg overlays it.

        // -------- stage accumulators to SMEM (float2, stride LDS_=130) --------
        #pragma unroll
        for (int mf=0; mf<2; mf++){
            #pragma unroll
            for (int h=0; h<2; h++){
                const int row = rowW + mf*16 + h*8 + lr;
                float2* srow = reinterpret_cast<float2*>(Sg + row*LDS_);
                #pragma unroll
                for (int nf=0; nf<8; nf++){
                    int nloc = (colW + nf*8) >> 1;
                    srow[nloc + lc] = make_float2(acc[mf][nf][h*2], acc[mf][nf][h*2+1]);
                }
            }
        }
        __syncthreads();

        // -------- coalesced stores: 2 rows x 128 cols per iteration --------
        {
            const int col = tid & 127;
            const int r0  = tid >> 7;       // 0 or 1
            if (full){
                #pragma unroll 8
                for (int rr = r0; rr < 128; rr += 2){
                    out[(size_t)(mBase + rr) * V_ + nBase + col] = Sg[rr*LDS_ + col];
                }
            } else if (col < nValid){
                for (int rr = r0; rr < 128; rr += 2){
                    out[(size_t)(mBase + rr) * V_ + nBase + col] = Sg[rr*LDS_ + col];
                }
            }
        }
        __syncthreads();   // stage reads done before next B tile overwrites
    }
}

// ---------------- K4: merge partials -> lse per row ----------------
__global__ void k_lse(){
    const int row = blockIdx.x;
    const int t = threadIdx.x;  // 128
    float m = neg_inf(), s = 0.f;
    for (int i = t; i < NCB; i += 128){
        float pm = g_pmax[row*NCB + i];
        float ps = g_psum[row*NCB + i];
        if (pm > m){ s = s*__expf(m - pm) + ps; m = pm; }
        else       { s += ps*__expf(pm - m); }
    }
    #pragma unroll
    for (int o = 16; o; o >>= 1){
        float om = __shfl_xor_sync(0xffffffffu, m, o);
        float os = __shfl_xor_sync(0xffffffffu, s, o);
        if (om > m){ s = s*__expf(m - om) + os; m = om; }
        else       { s += os*__expf(om - m); }
    }
    __shared__ float wm[4], ws[4];
    if ((t & 31) == 0){ wm[t>>5] = m; ws[t>>5] = s; }
    __syncthreads();
    if (t == 0){
        m = wm[0]; s = ws[0];
        #pragma unroll
        for (int w = 1; w < 4; w++){
            float om = wm[w], os = ws[w];
            if (om > m){ s = s*__expf(m - om) + os; m = om; }
            else       { s += os*__expf(om - m); }
        }
        g_lse[row] = m + logf(s);
    }
}

// ---------------- K5: out -= lse[row] ----------------
__global__ void k_fix(float* __restrict__ out){
    const int row = blockIdx.y;
    const float l = g_lse[row];
    float* o = out + (size_t)row * V_;
    const int base = blockIdx.x*1024 + threadIdx.x;
    #pragma unroll
    for (int j = 0; j < 4; j++){
        int c = base + j*256;
        if (c < V_) o[c] -= l;
    }
}

// ---------------- launch ----------------
extern "C" void kernel_launch(void* const* d_in, const int* in_sizes, int n_in,
                              void* d_out, int out_size){
    const float* xs     = (const float*)d_in[0];
    const float* metric = (const float*)d_in[1];
    const float* EM     = (const float*)d_in[2];
    const float* NEG    = (const float*)d_in[3];
    float* out = (float*)d_out;

    cudaFuncSetAttribute(k_gemm, cudaFuncAttributeMaxDynamicSharedMemorySize, GEMM_SMEM);

    k_find <<<4096, 256>>>(xs);
    k_embed<<<B_, E_>>>(EM, metric);
    k_gemm <<<dim3(NSPLIT, B_/128), 256, GEMM_SMEM>>>(NEG, out);
    k_lse  <<<B_, 128>>>();
    k_fix  <<<dim3((V_ + 1023)/1024, B_), 256>>>(out);
}

// round 9
// speedup vs baseline: 1.4625x; 1.0070x over previous
#include <cuda_runtime.h>
#include <cuda_fp16.h>
#include <cstdint>

#define B_   1024
#define V_   50257
#define E_   128
#define NCB  393            // ceil(V_/128)
#define NSPLIT 36           // N strips -> grid.x (288 CTAs = 2/SM)
#define LDH  136            // halves per smem row (128 + 8 pad)
#define LDW  68             // uint32 (half2) stride
#define TILE_BYTES (128*LDH*2)      // 34816 (A and B tiles)
#define LDS_  130           // stage stride in floats
#define STAGE_BYTES (128*LDS_*4)    // 66560
#define GEMM_SMEM (TILE_BYTES + STAGE_BYTES)  // A + max(B, stage) = 101376

__device__ int   g_idx[B_];
__device__ __align__(16) float g_H[B_*E_];
__device__ float g_pmax[B_*NCB];
__device__ float g_psum[B_*NCB];
__device__ float g_lse[B_];

__device__ __forceinline__ float neg_inf(){ return __int_as_float(0xff800000); }

__device__ __forceinline__ uint32_t pack2(float x, float y){
    __half2 h = __floats2half2_rn(x, y);
    return *reinterpret_cast<uint32_t*>(&h);
}
__device__ __forceinline__ uint32_t smem_u32(const void* p){
    uint32_t a;
    asm("{ .reg .u64 t; cvta.to.shared.u64 t, %1; cvt.u32.u64 %0, t; }" : "=r"(a) : "l"(p));
    return a;
}
__device__ __forceinline__ void ldsm4(uint32_t& r0, uint32_t& r1, uint32_t& r2, uint32_t& r3, uint32_t addr){
    asm volatile("ldmatrix.sync.aligned.m8n8.x4.shared.b16 {%0,%1,%2,%3}, [%4];"
                 : "=r"(r0), "=r"(r1), "=r"(r2), "=r"(r3) : "r"(addr));
}

// ---------------- K1: find one-hot index per row ----------------
__global__ void k_find(const float* __restrict__ xs){
    const int nf4 = (B_*V_)/4;
    for (int i = blockIdx.x*blockDim.x + threadIdx.x; i < nf4; i += gridDim.x*blockDim.x){
        float4 v = reinterpret_cast<const float4*>(xs)[i];
        if (v.x!=0.f || v.y!=0.f || v.z!=0.f || v.w!=0.f){
            float a[4] = {v.x, v.y, v.z, v.w};
            #pragma unroll
            for (int j = 0; j < 4; j++){
                if (a[j] != 0.f){
                    int f = i*4 + j;
                    g_idx[f / V_] = f % V_;
                }
            }
        }
    }
}

// ---------------- K2: H = EMBEDM[idx] @ metric ----------------
__global__ void k_embed(const float* __restrict__ EM, const float* __restrict__ metric){
    __shared__ float e[E_];
    const int row = blockIdx.x, t = threadIdx.x;
    e[t] = EM[(size_t)g_idx[row]*E_ + t];
    __syncthreads();
    float acc = 0.f;
    #pragma unroll 8
    for (int k = 0; k < E_; k++) acc += e[k] * metric[k*E_ + t];
    g_H[row*E_ + t] = acc;
}

// ---------------- K3: persistent fp16 GEMM + partial softmax stats ----------------
// grid (NSPLIT, 8), 256 thr = 8 warps, warp tile 16(M) x 128(N) -> each warp owns
// whole output rows (softmax stats = quad shuffles only, no cross-warp smem).
// ldmatrix fragment loads; mma.sync.m16n8k16.f16.f32; 2 CTAs/SM; staged coalesced stores.
__global__ void __launch_bounds__(256,2) k_gemm(const float* __restrict__ neg, float* __restrict__ out){
    extern __shared__ __align__(16) unsigned char smraw[];
    uint32_t* Au = reinterpret_cast<uint32_t*>(smraw);               // A: [128][LDH] halves
    uint32_t* Bu = reinterpret_cast<uint32_t*>(smraw + TILE_BYTES);  // B: [128][LDH] halves
    float*    Sg = reinterpret_cast<float*>(smraw + TILE_BYTES);     // stage overlays B (post-MMA)

    const int tid   = threadIdx.x;
    const int mBase = blockIdx.y * 128;
    const int gx    = blockIdx.x;

    const int warp = tid >> 5, lane = tid & 31;
    const int rowW = warp * 16;
    const int lr = lane >> 2, lc = lane & 3;

    const uint32_t aBase = smem_u32(Au);
    const uint32_t bBase = smem_u32(Bu);

    // ldmatrix per-lane addresses
    const int mat = lane >> 3, mrow = lane & 7;
    // A x4: matrices (m0..7,k0..7),(m8..15,k0..7),(m0..7,k8..15),(m8..15,k8..15) -> a0..a3
    const uint32_t aAddr0 = aBase +
        (uint32_t)(((rowW + ((mat & 1) << 3) + mrow) * LDH) + ((mat >> 1) << 3)) * 2u;
    // B x4 per np: matrices (n0..7,k0..7),(n0..7,k8..15),(n8..15,k0..7),(n8..15,k8..15)
    //   -> b[2np][0], b[2np][1], b[2np+1][0], b[2np+1][1]
    const uint32_t bAddr0 = bBase +
        (uint32_t)(((((mat >> 1) << 3) + mrow) * LDH) + ((mat & 1) << 3)) * 2u;

    // ---- A tile once: f32 -> f16 (RN) ----
    {
        const float4* aSrc = reinterpret_cast<const float4*>(g_H + (size_t)mBase*E_);
        #pragma unroll 4
        for (int i = tid; i < 4096; i += 256){
            float4 v = aSrc[i];
            int row = i >> 5, c4 = (i & 31) << 2;
            uint2 w = make_uint2(pack2(v.x, v.y), pack2(v.z, v.w));
            *reinterpret_cast<uint2*>(Au + row*LDW + (c4 >> 1)) = w;
        }
    }

    for (int nb = gx; nb < NCB; nb += NSPLIT){
        const int nBase = nb * 128;
        const int nValid = (V_ - nBase < 128) ? (V_ - nBase) : 128;
        const bool full = (nValid == 128);

        // ---- B tile: f32 LDG -> f16 -> STS (zero pad past V_) ----
        #pragma unroll 4
        for (int i = tid; i < 4096; i += 256){
            int row = i >> 5, c4 = (i & 31) << 2;
            int n = nBase + row;
            float4 v = make_float4(0.f, 0.f, 0.f, 0.f);
            if (n < V_) v = *reinterpret_cast<const float4*>(neg + (size_t)n*E_ + c4);
            uint2 w = make_uint2(pack2(v.x, v.y), pack2(v.z, v.w));
            *reinterpret_cast<uint2*>(Bu + row*LDW + (c4 >> 1)) = w;
        }
        __syncthreads();

        float acc[16][4];
        #pragma unroll
        for (int nf=0; nf<16; nf++)
            #pragma unroll
            for (int r=0; r<4; r++) acc[nf][r] = 0.f;

        #pragma unroll
        for (int ks = 0; ks < 8; ks++){
            const uint32_t kOff = (uint32_t)ks * 32u;   // 16 halves
            uint32_t a0, a1, a2, a3;
            ldsm4(a0, a1, a2, a3, aAddr0 + kOff);
            uint32_t b[16][2];
            #pragma unroll
            for (int np = 0; np < 8; np++)
                ldsm4(b[2*np][0], b[2*np][1], b[2*np+1][0], b[2*np+1][1],
                      bAddr0 + (uint32_t)np * (16u*LDH*2u) + kOff);
            #pragma unroll
            for (int nf = 0; nf < 16; nf++)
                asm volatile(
                    "mma.sync.aligned.m16n8k16.row.col.f32.f16.f16.f32 "
                    "{%0,%1,%2,%3},{%4,%5,%6,%7},{%8,%9},{%0,%1,%2,%3};"
                    : "+f"(acc[nf][0]), "+f"(acc[nf][1]),
                      "+f"(acc[nf][2]), "+f"(acc[nf][3])
                    : "r"(a0), "r"(a1), "r"(a2), "r"(a3),
                      "r"(b[nf][0]), "r"(b[nf][1]));
        }
        __syncthreads();   // all warps done with B tile (stage will overlay it)

        // -------- softmax stats: each warp owns its rows; quad shuffles only --------
        #pragma unroll
        for (int h = 0; h < 2; h++){
            const int row = rowW + h*8 + lr;
            float m = neg_inf();
            #pragma unroll
            for (int nf = 0; nf < 16; nf++){
                int n0 = nBase + nf*8 + lc*2;
                float v0 = acc[nf][h*2], v1 = acc[nf][h*2+1];
                if (full || n0   < V_) m = fmaxf(m, v0);
                if (full || n0+1 < V_) m = fmaxf(m, v1);
            }
            m = fmaxf(m, __shfl_xor_sync(0xffffffffu, m, 1));
            m = fmaxf(m, __shfl_xor_sync(0xffffffffu, m, 2));
            float s = 0.f;
            #pragma unroll
            for (int nf = 0; nf < 16; nf++){
                int n0 = nBase + nf*8 + lc*2;
                float v0 = acc[nf][h*2], v1 = acc[nf][h*2+1];
                if (full || n0   < V_) s += __expf(v0 - m);
                if (full || n0+1 < V_) s += __expf(v1 - m);
            }
            s += __shfl_xor_sync(0xffffffffu, s, 1);
            s += __shfl_xor_sync(0xffffffffu, s, 2);
            if (lc == 0){
                const int gr = mBase + row;
                g_pmax[gr*NCB + nb] = m;
                g_psum[gr*NCB + nb] = s;
            }
        }

        // -------- stage accumulators (float2, stride LDS_=130) --------
        #pragma unroll
        for (int h = 0; h < 2; h++){
            const int row = rowW + h*8 + lr;
            float2* srow = reinterpret_cast<float2*>(Sg + row*LDS_);
            #pragma unroll
            for (int nf = 0; nf < 16; nf++)
                srow[nf*4 + lc] = make_float2(acc[nf][h*2], acc[nf][h*2+1]);
        }
        __syncthreads();

        // -------- coalesced stores: 2 rows x 128 cols per iteration --------
        {
            const int col = tid & 127;
            const int r0  = tid >> 7;       // 0 or 1
            if (full){
                #pragma unroll 8
                for (int rr = r0; rr < 128; rr += 2)
                    out[(size_t)(mBase + rr) * V_ + nBase + col] = Sg[rr*LDS_ + col];
            } else if (col < nValid){
                for (int rr = r0; rr < 128; rr += 2)
                    out[(size_t)(mBase + rr) * V_ + nBase + col] = Sg[rr*LDS_ + col];
            }
        }
        __syncthreads();   // stage reads done before next B tile overwrites
    }
}

// ---------------- K4: merge partials -> lse per row ----------------
__global__ void k_lse(){
    const int row = blockIdx.x;
    const int t = threadIdx.x;  // 128
    float m = neg_inf(), s = 0.f;
    for (int i = t; i < NCB; i += 128){
        float pm = g_pmax[row*NCB + i];
        float ps = g_psum[row*NCB + i];
        if (pm > m){ s = s*__expf(m - pm) + ps; m = pm; }
        else       { s += ps*__expf(pm - m); }
    }
    #pragma unroll
    for (int o = 16; o; o >>= 1){
        float om = __shfl_xor_sync(0xffffffffu, m, o);
        float os = __shfl_xor_sync(0xffffffffu, s, o);
        if (om > m){ s = s*__expf(m - om) + os; m = om; }
        else       { s += os*__expf(om - m); }
    }
    __shared__ float wm[4], ws[4];
    if ((t & 31) == 0){ wm[t>>5] = m; ws[t>>5] = s; }
    __syncthreads();
    if (t == 0){
        m = wm[0]; s = ws[0];
        #pragma unroll
        for (int w = 1; w < 4; w++){
            float om = wm[w], os = ws[w];
            if (om > m){ s = s*__expf(m - om) + os; m = om; }
            else       { s += os*__expf(om - m); }
        }
        g_lse[row] = m + logf(s);
    }
}

// ---------------- K5: out -= lse[row] ----------------
__global__ void k_fix(float* __restrict__ out){
    const int row = blockIdx.y;
    const float l = g_lse[row];
    float* o = out + (size_t)row * V_;
    const int base = blockIdx.x*1024 + threadIdx.x;
    #pragma unroll
    for (int j = 0; j < 4; j++){
        int c = base + j*256;
        if (c < V_) o[c] -= l;
    }
}

// ---------------- launch ----------------
extern "C" void kernel_launch(void* const* d_in, const int* in_sizes, int n_in,
                              void* d_out, int out_size){
    const float* xs     = (const float*)d_in[0];
    const float* metric = (const float*)d_in[1];
    const float* EM     = (const float*)d_in[2];
    const float* NEG    = (const float*)d_in[3];
    float* out = (float*)d_out;

    cudaFuncSetAttribute(k_gemm, cudaFuncAttributeMaxDynamicSharedMemorySize, GEMM_SMEM);

    k_find <<<4096, 256>>>(xs);
    k_embed<<<B_, E_>>>(EM, metric);
    k_gemm <<<dim3(NSPLIT, B_/128), 256, GEMM_SMEM>>>(NEG, out);
    k_lse  <<<B_, 128>>>();
    k_fix  <<<dim3((V_ + 1023)/1024, B_), 256>>>(out);
}

// round 11
// speedup vs baseline: 1.5490x; 1.0592x over previous
#include <cuda_runtime.h>
#include <cuda_fp16.h>
#include <cstdint>

#define B_   1024
#define V_   50257
#define E_   128
#define NCB  393            // ceil(V_/128)
#define NSPLIT 36           // N strips -> grid.x (288 CTAs = 2/SM)
#define LDH  136            // halves per smem row (128 + 8 pad)
#define LDW  68             // uint32 (half2) stride
#define TILE_BYTES (128*LDH*2)      // 34816 (A and B tiles)
#define LDS_  130           // stage stride in floats
#define STAGE_BYTES (128*LDS_*4)    // 66560
#define GEMM_SMEM (TILE_BYTES + STAGE_BYTES)  // A + max(B, stage) = 101376
#define LOG2E 1.4426950408889634f

__device__ int   g_idx[B_];
__device__ __align__(16) float g_H[B_*E_];
__device__ float g_pmax[B_*NCB];
__device__ float g_psum[B_*NCB];
__device__ float g_lse[B_];

__device__ __forceinline__ float neg_inf(){ return __int_as_float(0xff800000); }

__device__ __forceinline__ uint32_t pack2(float x, float y){
    __half2 h = __floats2half2_rn(x, y);
    return *reinterpret_cast<uint32_t*>(&h);
}
__device__ __forceinline__ uint32_t smem_u32(const void* p){
    uint32_t a;
    asm("{ .reg .u64 t; cvta.to.shared.u64 t, %1; cvt.u32.u64 %0, t; }" : "=r"(a) : "l"(p));
    return a;
}
__device__ __forceinline__ void ldsm4(uint32_t& r0, uint32_t& r1, uint32_t& r2, uint32_t& r3, uint32_t addr){
    asm volatile("ldmatrix.sync.aligned.m8n8.x4.shared.b16 {%0,%1,%2,%3}, [%4];"
                 : "=r"(r0), "=r"(r1), "=r"(r2), "=r"(r3) : "r"(addr));
}
// two exps in one MUFU op: returns half2(exp2(t0), exp2(t1))
__device__ __forceinline__ __half2 exp2_pair(float t0, float t1){
    uint32_t hx, he;
    asm("cvt.rn.f16x2.f32 %0, %1, %2;" : "=r"(hx) : "f"(t1), "f"(t0));
    asm("ex2.approx.f16x2 %0, %1;" : "=r"(he) : "r"(hx));
    return *reinterpret_cast<__half2*>(&he);
}

// ---------------- K1: find one-hot index per row ----------------
__global__ void k_find(const float* __restrict__ xs){
    const int nf4 = (B_*V_)/4;
    for (int i = blockIdx.x*blockDim.x + threadIdx.x; i < nf4; i += gridDim.x*blockDim.x){
        float4 v = reinterpret_cast<const float4*>(xs)[i];
        if (v.x!=0.f || v.y!=0.f || v.z!=0.f || v.w!=0.f){
            float a[4] = {v.x, v.y, v.z, v.w};
            #pragma unroll
            for (int j = 0; j < 4; j++){
                if (a[j] != 0.f){
                    int f = i*4 + j;
                    g_idx[f / V_] = f % V_;
                }
            }
        }
    }
}

// ---------------- K2: H = EMBEDM[idx] @ metric ----------------
__global__ void k_embed(const float* __restrict__ EM, const float* __restrict__ metric){
    __shared__ float e[E_];
    const int row = blockIdx.x, t = threadIdx.x;
    e[t] = EM[(size_t)g_idx[row]*E_ + t];
    __syncthreads();
    float acc = 0.f;
    #pragma unroll 8
    for (int k = 0; k < E_; k++) acc += e[k] * metric[k*E_ + t];
    g_H[row*E_ + t] = acc;
}

// ---------------- K3: persistent fp16 GEMM + partial softmax stats ----------------
// grid (NSPLIT, 8), 256 thr = 8 warps, warp tile 16(M) x 128(N).
// ldmatrix fragments; mma.sync.m16n8k16.f16.f32; 2 CTAs/SM; staged coalesced stores;
// softmax sumexp via ex2.approx.f16x2 (2 exps / MUFU op).
__global__ void __launch_bounds__(256,2) k_gemm(const float* __restrict__ neg, float* __restrict__ out){
    extern __shared__ __align__(16) unsigned char smraw[];
    uint32_t* Au = reinterpret_cast<uint32_t*>(smraw);               // A: [128][LDH] halves
    uint32_t* Bu = reinterpret_cast<uint32_t*>(smraw + TILE_BYTES);  // B: [128][LDH] halves
    float*    Sg = reinterpret_cast<float*>(smraw + TILE_BYTES);     // stage overlays B (post-MMA)

    const int tid   = threadIdx.x;
    const int mBase = blockIdx.y * 128;
    const int gx    = blockIdx.x;

    const int warp = tid >> 5, lane = tid & 31;
    const int rowW = warp * 16;
    const int lr = lane >> 2, lc = lane & 3;

    const uint32_t aBase = smem_u32(Au);
    const uint32_t bBase = smem_u32(Bu);

    const int mat = lane >> 3, mrow = lane & 7;
    const uint32_t aAddr0 = aBase +
        (uint32_t)(((rowW + ((mat & 1) << 3) + mrow) * LDH) + ((mat >> 1) << 3)) * 2u;
    const uint32_t bAddr0 = bBase +
        (uint32_t)(((((mat >> 1) << 3) + mrow) * LDH) + ((mat & 1) << 3)) * 2u;

    // ---- A tile once: f32 -> f16 (RN) ----
    {
        const float4* aSrc = reinterpret_cast<const float4*>(g_H + (size_t)mBase*E_);
        #pragma unroll 4
        for (int i = tid; i < 4096; i += 256){
            float4 v = aSrc[i];
            int row = i >> 5, c4 = (i & 31) << 2;
            uint2 w = make_uint2(pack2(v.x, v.y), pack2(v.z, v.w));
            *reinterpret_cast<uint2*>(Au + row*LDW + (c4 >> 1)) = w;
        }
    }

    for (int nb = gx; nb < NCB; nb += NSPLIT){
        const int nBase = nb * 128;
        const int nValid = (V_ - nBase < 128) ? (V_ - nBase) : 128;
        const bool full = (nValid == 128);

        // ---- B tile: f32 LDG -> f16 -> STS (zero pad past V_) ----
        #pragma unroll 4
        for (int i = tid; i < 4096; i += 256){
            int row = i >> 5, c4 = (i & 31) << 2;
            int n = nBase + row;
            float4 v = make_float4(0.f, 0.f, 0.f, 0.f);
            if (n < V_) v = *reinterpret_cast<const float4*>(neg + (size_t)n*E_ + c4);
            uint2 w = make_uint2(pack2(v.x, v.y), pack2(v.z, v.w));
            *reinterpret_cast<uint2*>(Bu + row*LDW + (c4 >> 1)) = w;
        }
        __syncthreads();

        float acc[16][4];
        #pragma unroll
        for (int nf=0; nf<16; nf++)
            #pragma unroll
            for (int r=0; r<4; r++) acc[nf][r] = 0.f;

        #pragma unroll
        for (int ks = 0; ks < 8; ks++){
            const uint32_t kOff = (uint32_t)ks * 32u;   // 16 halves
            uint32_t a0, a1, a2, a3;
            ldsm4(a0, a1, a2, a3, aAddr0 + kOff);
            uint32_t b[16][2];
            #pragma unroll
            for (int np = 0; np < 8; np++)
                ldsm4(b[2*np][0], b[2*np][1], b[2*np+1][0], b[2*np+1][1],
                      bAddr0 + (uint32_t)np * (16u*LDH*2u) + kOff);
            #pragma unroll
            for (int nf = 0; nf < 16; nf++)
                asm volatile(
                    "mma.sync.aligned.m16n8k16.row.col.f32.f16.f16.f32 "
                    "{%0,%1,%2,%3},{%4,%5,%6,%7},{%8,%9},{%0,%1,%2,%3};"
                    : "+f"(acc[nf][0]), "+f"(acc[nf][1]),
                      "+f"(acc[nf][2]), "+f"(acc[nf][3])
                    : "r"(a0), "r"(a1), "r"(a2), "r"(a3),
                      "r"(b[nf][0]), "r"(b[nf][1]));
        }
        __syncthreads();   // all warps done with B tile (stage will overlay it)

        // -------- softmax stats: per-warp rows, quad shuffles; exp via ex2.f16x2 --------
        if (full){
            #pragma unroll
            for (int h = 0; h < 2; h++){
                const int row = rowW + h*8 + lr;
                float m = neg_inf();
                #pragma unroll
                for (int nf = 0; nf < 16; nf++)
                    m = fmaxf(m, fmaxf(acc[nf][h*2], acc[nf][h*2+1]));
                m = fmaxf(m, __shfl_xor_sync(0xffffffffu, m, 1));
                m = fmaxf(m, __shfl_xor_sync(0xffffffffu, m, 2));
                const float c = -m * LOG2E;
                float s = 0.f;
                #pragma unroll
                for (int nf = 0; nf < 16; nf += 4){
                    __half2 hs = __float2half2_rn(0.f);
                    #pragma unroll
                    for (int q = 0; q < 4; q++){
                        float t0 = fmaf(acc[nf+q][h*2],   LOG2E, c);
                        float t1 = fmaf(acc[nf+q][h*2+1], LOG2E, c);
                        hs = __hadd2(hs, exp2_pair(t0, t1));
                    }
                    float2 f2 = __half22float2(hs);
                    s += f2.x + f2.y;
                }
                s += __shfl_xor_sync(0xffffffffu, s, 1);
                s += __shfl_xor_sync(0xffffffffu, s, 2);
                if (lc == 0){
                    const int gr = mBase + row;
                    g_pmax[gr*NCB + nb] = m;
                    g_psum[gr*NCB + nb] = s;
                }
            }
        } else {
            #pragma unroll
            for (int h = 0; h < 2; h++){
                const int row = rowW + h*8 + lr;
                float m = neg_inf();
                #pragma unroll
                for (int nf = 0; nf < 16; nf++){
                    int n0 = nBase + nf*8 + lc*2;
                    if (n0   < V_) m = fmaxf(m, acc[nf][h*2]);
                    if (n0+1 < V_) m = fmaxf(m, acc[nf][h*2+1]);
                }
                m = fmaxf(m, __shfl_xor_sync(0xffffffffu, m, 1));
                m = fmaxf(m, __shfl_xor_sync(0xffffffffu, m, 2));
                float s = 0.f;
                #pragma unroll
                for (int nf = 0; nf < 16; nf++){
                    int n0 = nBase + nf*8 + lc*2;
                    if (n0   < V_) s += __expf(acc[nf][h*2]   - m);
                    if (n0+1 < V_) s += __expf(acc[nf][h*2+1] - m);
                }
                s += __shfl_xor_sync(0xffffffffu, s, 1);
                s += __shfl_xor_sync(0xffffffffu, s, 2);
                if (lc == 0){
                    const int gr = mBase + row;
                    g_pmax[gr*NCB + nb] = m;
                    g_psum[gr*NCB + nb] = s;
                }
            }
        }

        // -------- stage accumulators (float2, stride LDS_=130) --------
        #pragma unroll
        for (int h = 0; h < 2; h++){
            const int row = rowW + h*8 + lr;
            float2* srow = reinterpret_cast<float2*>(Sg + row*LDS_);
            #pragma unroll
            for (int nf = 0; nf < 16; nf++)
                srow[nf*4 + lc] = make_float2(acc[nf][h*2], acc[nf][h*2+1]);
        }
        __syncthreads();

        // -------- coalesced stores: 2 rows x 128 cols per iteration --------
        {
            const int col = tid & 127;
            const int r0  = tid >> 7;       // 0 or 1
            if (full){
                #pragma unroll 8
                for (int rr = r0; rr < 128; rr += 2)
                    out[(size_t)(mBase + rr) * V_ + nBase + col] = Sg[rr*LDS_ + col];
            } else if (col < nValid){
                for (int rr = r0; rr < 128; rr += 2)
                    out[(size_t)(mBase + rr) * V_ + nBase + col] = Sg[rr*LDS_ + col];
            }
        }
        __syncthreads();   // stage reads done before next B tile overwrites
    }
}

// ---------------- K4: merge partials -> lse per row ----------------
__global__ void k_lse(){
    const int row = blockIdx.x;
    const int t = threadIdx.x;  // 128
    float m = neg_inf(), s = 0.f;
    for (int i = t; i < NCB; i += 128){
        float pm = g_pmax[row*NCB + i];
        float ps = g_psum[row*NCB + i];
        if (pm > m){ s = s*__expf(m - pm) + ps; m = pm; }
        else       { s += ps*__expf(pm - m); }
    }
    #pragma unroll
    for (int o = 16; o; o >>= 1){
        float om = __shfl_xor_sync(0xffffffffu, m, o);
        float os = __shfl_xor_sync(0xffffffffu, s, o);
        if (om > m){ s = s*__expf(m - om) + os; m = om; }
        else       { s += os*__expf(om - m); }
    }
    __shared__ float wm[4], ws[4];
    if ((t & 31) == 0){ wm[t>>5] = m; ws[t>>5] = s; }
    __syncthreads();
    if (t == 0){
        m = wm[0]; s = ws[0];
        #pragma unroll
        for (int w = 1; w < 4; w++){
            float om = wm[w], os = ws[w];
            if (om > m){ s = s*__expf(m - om) + os; m = om; }
            else       { s += os*__expf(om - m); }
        }
        g_lse[row] = m + logf(s);
    }
}

// ---------------- K5: out -= lse[row] ----------------
__global__ void k_fix(float* __restrict__ out){
    const int row = blockIdx.y;
    const float l = g_lse[row];
    float* o = out + (size_t)row * V_;
    const int base = blockIdx.x*1024 + threadIdx.x;
    #pragma unroll
    for (int j = 0; j < 4; j++){
        int c = base + j*256;
        if (c < V_) o[c] -= l;
    }
}

// ---------------- launch ----------------
extern "C" void kernel_launch(void* const* d_in, const int* in_sizes, int n_in,
                              void* d_out, int out_size){
    const float* xs     = (const float*)d_in[0];
    const float* metric = (const float*)d_in[1];
    const float* EM     = (const float*)d_in[2];
    const float* NEG    = (const float*)d_in[3];
    float* out = (float*)d_out;

    cudaFuncSetAttribute(k_gemm, cudaFuncAttributeMaxDynamicSharedMemorySize, GEMM_SMEM);

    k_find <<<4096, 256>>>(xs);
    k_embed<<<B_, E_>>>(EM, metric);
    k_gemm <<<dim3(NSPLIT, B_/128), 256, GEMM_SMEM>>>(NEG, out);
    k_lse  <<<B_, 128>>>();
    k_fix  <<<dim3((V_ + 1023)/1024, B_), 256>>>(out);
}

// round 13
// speedup vs baseline: 1.8323x; 1.1829x over previous
#include <cuda_runtime.h>
#include <cuda_fp16.h>
#include <cstdint>

#define B_   1024
#define V_   50257
#define E_   128
#define NCB  393            // ceil(V_/128)
#define NSPLIT 37           // N strips -> grid.x (296 CTAs = exactly 2/SM on 148 SMs)
#define LDH  136            // halves per smem row (128 + 8 pad)
#define LDW  68             // uint32 (half2) stride
#define TILE_BYTES (128*LDH*2)      // 34816 (A and B tiles)
#define LDS_  130           // stage stride in floats
#define STAGE_BYTES (128*LDS_*4)    // 66560
#define GEMM_SMEM (TILE_BYTES + STAGE_BYTES)  // A + max(B, stage) = 101376
#define LOG2E 1.4426950408889634f

__device__ int   g_idx[B_];
__device__ __align__(16) float g_H[B_*E_];
__device__ float g_pmax[B_*NCB];
__device__ float g_psum[B_*NCB];

__device__ __forceinline__ float neg_inf(){ return __int_as_float(0xff800000); }

__device__ __forceinline__ uint32_t pack2(float x, float y){
    __half2 h = __floats2half2_rn(x, y);
    return *reinterpret_cast<uint32_t*>(&h);
}
__device__ __forceinline__ uint32_t smem_u32(const void* p){
    uint32_t a;
    asm("{ .reg .u64 t; cvta.to.shared.u64 t, %1; cvt.u32.u64 %0, t; }" : "=r"(a) : "l"(p));
    return a;
}
__device__ __forceinline__ void ldsm4(uint32_t& r0, uint32_t& r1, uint32_t& r2, uint32_t& r3, uint32_t addr){
    asm volatile("ldmatrix.sync.aligned.m8n8.x4.shared.b16 {%0,%1,%2,%3}, [%4];"
                 : "=r"(r0), "=r"(r1), "=r"(r2), "=r"(r3) : "r"(addr));
}
// two exps in one MUFU op: returns half2(exp2(t0), exp2(t1))
__device__ __forceinline__ __half2 exp2_pair(float t0, float t1){
    uint32_t hx, he;
    asm("cvt.rn.f16x2.f32 %0, %1, %2;" : "=r"(hx) : "f"(t1), "f"(t0));
    asm("ex2.approx.f16x2 %0, %1;" : "=r"(he) : "r"(hx));
    return *reinterpret_cast<__half2*>(&he);
}

// ---------------- K1: find one-hot index per row ----------------
__global__ void k_find(const float* __restrict__ xs){
    const int nf4 = (B_*V_)/4;
    for (int i = blockIdx.x*blockDim.x + threadIdx.x; i < nf4; i += gridDim.x*blockDim.x){
        float4 v = reinterpret_cast<const float4*>(xs)[i];
        if (v.x!=0.f || v.y!=0.f || v.z!=0.f || v.w!=0.f){
            float a[4] = {v.x, v.y, v.z, v.w};
            #pragma unroll
            for (int j = 0; j < 4; j++){
                if (a[j] != 0.f){
                    int f = i*4 + j;
                    g_idx[f / V_] = f % V_;
                }
            }
        }
    }
}

// ---------------- K2: H = EMBEDM[idx] @ metric ----------------
__global__ void k_embed(const float* __restrict__ EM, const float* __restrict__ metric){
    __shared__ float e[E_];
    const int row = blockIdx.x, t = threadIdx.x;
    e[t] = EM[(size_t)g_idx[row]*E_ + t];
    __syncthreads();
    float acc = 0.f;
    #pragma unroll 8
    for (int k = 0; k < E_; k++) acc += e[k] * metric[k*E_ + t];
    g_H[row*E_ + t] = acc;
}

// ---------------- K3: persistent fp16 GEMM + partial softmax stats ----------------
__global__ void __launch_bounds__(256,2) k_gemm(const float* __restrict__ neg, float* __restrict__ out){
    extern __shared__ __align__(16) unsigned char smraw[];
    uint32_t* Au = reinterpret_cast<uint32_t*>(smraw);               // A: [128][LDH] halves
    uint32_t* Bu = reinterpret_cast<uint32_t*>(smraw + TILE_BYTES);  // B: [128][LDH] halves
    float*    Sg = reinterpret_cast<float*>(smraw + TILE_BYTES);     // stage overlays B (post-MMA)

    const int tid   = threadIdx.x;
    const int mBase = blockIdx.y * 128;
    const int gx    = blockIdx.x;

    const int warp = tid >> 5, lane = tid & 31;
    const int rowW = warp * 16;
    const int lr = lane >> 2, lc = lane & 3;

    const uint32_t aBase = smem_u32(Au);
    const uint32_t bBase = smem_u32(Bu);

    const int mat = lane >> 3, mrow = lane & 7;
    const uint32_t aAddr0 = aBase +
        (uint32_t)(((rowW + ((mat & 1) << 3) + mrow) * LDH) + ((mat >> 1) << 3)) * 2u;
    const uint32_t bAddr0 = bBase +
        (uint32_t)(((((mat >> 1) << 3) + mrow) * LDH) + ((mat & 1) << 3)) * 2u;

    // ---- A tile once: f32 -> f16 (RN) ----
    {
        const float4* aSrc = reinterpret_cast<const float4*>(g_H + (size_t)mBase*E_);
        #pragma unroll 4
        for (int i = tid; i < 4096; i += 256){
            float4 v = aSrc[i];
            int row = i >> 5, c4 = (i & 31) << 2;
            uint2 w = make_uint2(pack2(v.x, v.y), pack2(v.z, v.w));
            *reinterpret_cast<uint2*>(Au + row*LDW + (c4 >> 1)) = w;
        }
    }

    for (int nb = gx; nb < NCB; nb += NSPLIT){
        const int nBase = nb * 128;
        const int nValid = (V_ - nBase < 128) ? (V_ - nBase) : 128;
        const bool full = (nValid == 128);

        // ---- B tile: f32 LDG -> f16 -> STS (zero pad past V_) ----
        #pragma unroll 4
        for (int i = tid; i < 4096; i += 256){
            int row = i >> 5, c4 = (i & 31) << 2;
            int n = nBase + row;
            float4 v = make_float4(0.f, 0.f, 0.f, 0.f);
            if (n < V_) v = *reinterpret_cast<const float4*>(neg + (size_t)n*E_ + c4);
            uint2 w = make_uint2(pack2(v.x, v.y), pack2(v.z, v.w));
            *reinterpret_cast<uint2*>(Bu + row*LDW + (c4 >> 1)) = w;
        }
        __syncthreads();

        float acc[16][4];
        #pragma unroll
        for (int nf=0; nf<16; nf++)
            #pragma unroll
            for (int r=0; r<4; r++) acc[nf][r] = 0.f;

        #pragma unroll
        for (int ks = 0; ks < 8; ks++){
            const uint32_t kOff = (uint32_t)ks * 32u;   // 16 halves
            uint32_t a0, a1, a2, a3;
            ldsm4(a0, a1, a2, a3, aAddr0 + kOff);
            uint32_t b[16][2];
            #pragma unroll
            for (int np = 0; np < 8; np++)
                ldsm4(b[2*np][0], b[2*np][1], b[2*np+1][0], b[2*np+1][1],
                      bAddr0 + (uint32_t)np * (16u*LDH*2u) + kOff);
            #pragma unroll
            for (int nf = 0; nf < 16; nf++)
                asm volatile(
                    "mma.sync.aligned.m16n8k16.row.col.f32.f16.f16.f32 "
                    "{%0,%1,%2,%3},{%4,%5,%6,%7},{%8,%9},{%0,%1,%2,%3};"
                    : "+f"(acc[nf][0]), "+f"(acc[nf][1]),
                      "+f"(acc[nf][2]), "+f"(acc[nf][3])
                    : "r"(a0), "r"(a1), "r"(a2), "r"(a3),
                      "r"(b[nf][0]), "r"(b[nf][1]));
        }
        __syncthreads();   // all warps done with B tile (stage will overlay it)

        // -------- softmax stats: per-warp rows, quad shuffles; exp via ex2.f16x2 --------
        if (full){
            #pragma unroll
            for (int h = 0; h < 2; h++){
                const int row = rowW + h*8 + lr;
                float m = neg_inf();
                #pragma unroll
                for (int nf = 0; nf < 16; nf++)
                    m = fmaxf(m, fmaxf(acc[nf][h*2], acc[nf][h*2+1]));
                m = fmaxf(m, __shfl_xor_sync(0xffffffffu, m, 1));
                m = fmaxf(m, __shfl_xor_sync(0xffffffffu, m, 2));
                const float c = -m * LOG2E;
                float s = 0.f;
                #pragma unroll
                for (int nf = 0; nf < 16; nf += 4){
                    __half2 hs = __float2half2_rn(0.f);
                    #pragma unroll
                    for (int q = 0; q < 4; q++){
                        float t0 = fmaf(acc[nf+q][h*2],   LOG2E, c);
                        float t1 = fmaf(acc[nf+q][h*2+1], LOG2E, c);
                        hs = __hadd2(hs, exp2_pair(t0, t1));
                    }
                    float2 f2 = __half22float2(hs);
                    s += f2.x + f2.y;
                }
                s += __shfl_xor_sync(0xffffffffu, s, 1);
                s += __shfl_xor_sync(0xffffffffu, s, 2);
                if (lc == 0){
                    const int gr = mBase + row;
                    g_pmax[gr*NCB + nb] = m;
                    g_psum[gr*NCB + nb] = s;
                }
            }
        } else {
            #pragma unroll
            for (int h = 0; h < 2; h++){
                const int row = rowW + h*8 + lr;
                float m = neg_inf();
                #pragma unroll
                for (int nf = 0; nf < 16; nf++){
                    int n0 = nBase + nf*8 + lc*2;
                    if (n0   < V_) m = fmaxf(m, acc[nf][h*2]);
                    if (n0+1 < V_) m = fmaxf(m, acc[nf][h*2+1]);
                }
                m = fmaxf(m, __shfl_xor_sync(0xffffffffu, m, 1));
                m = fmaxf(m, __shfl_xor_sync(0xffffffffu, m, 2));
                float s = 0.f;
                #pragma unroll
                for (int nf = 0; nf < 16; nf++){
                    int n0 = nBase + nf*8 + lc*2;
                    if (n0   < V_) s += __expf(acc[nf][h*2]   - m);
                    if (n0+1 < V_) s += __expf(acc[nf][h*2+1] - m);
                }
                s += __shfl_xor_sync(0xffffffffu, s, 1);
                s += __shfl_xor_sync(0xffffffffu, s, 2);
                if (lc == 0){
                    const int gr = mBase + row;
                    g_pmax[gr*NCB + nb] = m;
                    g_psum[gr*NCB + nb] = s;
                }
            }
        }

        // -------- stage accumulators (float2, stride LDS_=130) --------
        #pragma unroll
        for (int h = 0; h < 2; h++){
            const int row = rowW + h*8 + lr;
            float2* srow = reinterpret_cast<float2*>(Sg + row*LDS_);
            #pragma unroll
            for (int nf = 0; nf < 16; nf++)
                srow[nf*4 + lc] = make_float2(acc[nf][h*2], acc[nf][h*2+1]);
        }
        __syncthreads();

        // -------- coalesced stores: 2 rows x 128 cols per iteration --------
        {
            const int col = tid & 127;
            const int r0  = tid >> 7;       // 0 or 1
            if (full){
                #pragma unroll 8
                for (int rr = r0; rr < 128; rr += 2)
                    out[(size_t)(mBase + rr) * V_ + nBase + col] = Sg[rr*LDS_ + col];
            } else if (col < nValid){
                for (int rr = r0; rr < 128; rr += 2)
                    out[(size_t)(mBase + rr) * V_ + nBase + col] = Sg[rr*LDS_ + col];
            }
        }
        __syncthreads();   // stage reads done before next B tile overwrites
    }
}

// ---------------- K4: lse + fix fused, one block per row ----------------
__global__ void __launch_bounds__(256) k_fix2(float* __restrict__ out){
    const int row = blockIdx.x;
    const int t   = threadIdx.x;   // 256

    // ---- phase 1: merge 393 partials -> lse ----
    float m = neg_inf(), s = 0.f;
    for (int i = t; i < NCB; i += 256){
        float pm = g_pmax[row*NCB + i];
        float ps = g_psum[row*NCB + i];
        if (pm > m){ s = s*__expf(m - pm) + ps; m = pm; }
        else       { s += ps*__expf(pm - m); }
    }
    #pragma unroll
    for (int o = 16; o; o >>= 1){
        float om = __shfl_xor_sync(0xffffffffu, m, o);
        float os = __shfl_xor_sync(0xffffffffu, s, o);
        if (om > m){ s = s*__expf(m - om) + os; m = om; }
        else       { s += os*__expf(om - m); }
    }
    __shared__ float wm[8], ws[8], sh_lse;
    if ((t & 31) == 0){ wm[t>>5] = m; ws[t>>5] = s; }
    __syncthreads();
    if (t == 0){
        m = wm[0]; s = ws[0];
        #pragma unroll
        for (int w = 1; w < 8; w++){
            float om = wm[w], os = ws[w];
            if (om > m){ s = s*__expf(m - om) + os; m = om; }
            else       { s += os*__expf(om - m); }
        }
        sh_lse = m + logf(s);
    }
    __syncthreads();
    const float l = sh_lse;

    // ---- phase 2: out[row,:] -= l  (float4 with alignment peel; V_ odd) ----
    float* o = out + (size_t)row * V_;
    const int head = ((int)(((uintptr_t)o) >> 2)) & 3;   // floats past 16B boundary
    const int k0   = (4 - head) & 3;                     // scalar peel count
    if (t < k0) o[t] -= l;
    float4* o4 = reinterpret_cast<float4*>(o + k0);
    const int n4 = (V_ - k0) >> 2;
    for (int i = t; i < n4; i += 256){
        float4 v = o4[i];
        v.x -= l; v.y -= l; v.z -= l; v.w -= l;
        o4[i] = v;
    }
    const int tail = k0 + n4*4;
    const int trem = V_ - tail;
    if (t < trem) o[tail + t] -= l;
}

// ---------------- launch ----------------
extern "C" void kernel_launch(void* const* d_in, const int* in_sizes, int n_in,
                              void* d_out, int out_size){
    const float* xs     = (const float*)d_in[0];
    const float* metric = (const float*)d_in[1];
    const float* EM     = (const float*)d_in[2];
    const float* NEG    = (const float*)d_in[3];
    float* out = (float*)d_out;

    cudaFuncSetAttribute(k_gemm, cudaFuncAttributeMaxDynamicSharedMemorySize, GEMM_SMEM);

    k_find <<<4096, 256>>>(xs);
    k_embed<<<B_, E_>>>(EM, metric);
    k_gemm <<<dim3(NSPLIT, B_/128), 256, GEMM_SMEM>>>(NEG, out);
    k_fix2 <<<B_, 256>>>(out);
}